// round 4
// baseline (speedup 1.0000x reference)
#include <cuda_runtime.h>
#include <cuda_bf16.h>
#include <cstdint>

// Problem constants
#define B_IMG 4
#define H_IMG 224
#define W_IMG 224
#define C_IMG 3
#define N_SHIFT 21
#define N_ROT 5

// Padded float4 copy of the input: [B][H][W] -> float4(c0,c1,c2,0)
__device__ float4 g_xpad[B_IMG * H_IMG * W_IMG];

// Rotation cos/sin for ANGLES = [-0.5236, -0.2618, 0.0, 0.2618, 0.5236]
__constant__ float c_cos[N_ROT] = {0.86602479f, 0.96592567f, 1.0f, 0.96592567f, 0.86602479f};
__constant__ float c_sin[N_ROT] = {-0.50000106f, -0.25881964f, 0.0f, 0.25881964f, 0.50000106f};

// Shift sample offsets in pixels (ix_shift = x + sdx, iy_shift = y + sdy).
// Order: up p=1..5 (sdy=+p/2), down p=1..5 (sdy=-p/2),
//        left p=1..5 (sdx=+p/2), right p=1..5 (sdx=-p/2), right p=0.
__constant__ float c_sdx[N_SHIFT] = {
    0.f, 0.f, 0.f, 0.f, 0.f,
    0.f, 0.f, 0.f, 0.f, 0.f,
    0.5f, 1.0f, 1.5f, 2.0f, 2.5f,
    -0.5f, -1.0f, -1.5f, -2.0f, -2.5f,
    0.f};
__constant__ float c_sdy[N_SHIFT] = {
    0.5f, 1.0f, 1.5f, 2.0f, 2.5f,
    -0.5f, -1.0f, -1.5f, -2.0f, -2.5f,
    0.f, 0.f, 0.f, 0.f, 0.f,
    0.f, 0.f, 0.f, 0.f, 0.f,
    0.f};

// ---------------------------------------------------------------------------
// Kernel 1: repack NHWC float3 -> float4 plane (one LDG.128 per tap later)
// ---------------------------------------------------------------------------
__global__ void repack_kernel(const float* __restrict__ in) {
    int p = blockIdx.x * blockDim.x + threadIdx.x;
    const int total = B_IMG * H_IMG * W_IMG;
    if (p >= total) return;
    float c0 = in[p * 3 + 0];
    float c1 = in[p * 3 + 1];
    float c2 = in[p * 3 + 2];
    g_xpad[p] = make_float4(c0, c1, c2, 0.0f);
}

// ---------------------------------------------------------------------------
// Kernel 2: fused shift+rotate bilinear resample.
// One thread per output spatial pixel (3 channels).
// blockIdx.z = rs * B + b, rs = r * N_SHIFT + s  (matches output layout).
// ---------------------------------------------------------------------------
__global__ __launch_bounds__(256) void fused_transform_kernel(float* __restrict__ out) {
    const int x = blockIdx.x * 32 + threadIdx.x;
    const int y = blockIdx.y * 8 + threadIdx.y;
    const unsigned z = blockIdx.z;
    const unsigned b = z & 3u;          // B_IMG = 4
    const unsigned rs = z >> 2;
    const unsigned r = rs / N_SHIFT;    // -> umulhi reciprocal form
    const unsigned s = rs - r * N_SHIFT;

    // align_corners=True normalized grid
    const float inv = 2.0f / (float)(W_IMG - 1);   // H==W
    const float gx = fmaf((float)x, inv, -1.0f);
    const float gy = fmaf((float)y, inv, -1.0f);

    const float ca = c_cos[r];
    const float sa = c_sin[r];
    // theta row0 = [cos, sin, 0], row1 = [-sin, cos, 0]
    const float grid_x = gx * ca + gy * sa;
    const float grid_y = -gx * sa + gy * ca;

    const float half = 0.5f * (float)(W_IMG - 1);  // 111.5
    const float ix = (grid_x + 1.0f) * half;
    const float iy = (grid_y + 1.0f) * half;

    const float x0f = floorf(ix);
    const float y0f = floorf(iy);
    const float wx = ix - x0f;
    const float wy = iy - y0f;
    const int x0 = (int)x0f;
    const int y0 = (int)y0f;

    const float sdx = c_sdx[s];
    const float sdy = c_sdy[s];

    const float4* __restrict__ xb = g_xpad + b * (H_IMG * W_IMG);

    float accx = 0.f, accy = 0.f, accz = 0.f;

#pragma unroll
    for (int cy = 0; cy < 2; cy++) {
#pragma unroll
        for (int cx = 0; cx < 2; cx++) {
            const float wc = (cx ? wx : 1.0f - wx) * (cy ? wy : 1.0f - wy);
            const int xi = x0 + cx;
            const int yi = y0 + cy;
            if (wc != 0.0f && xi >= 0 && xi < W_IMG && yi >= 0 && yi < H_IMG) {
                // stage-1 (shift) sample of the source image at integer (yi, xi)
                const float ixs = (float)xi + sdx;
                const float iys = (float)yi + sdy;
                const float xs0f = floorf(ixs);
                const float ys0f = floorf(iys);
                const float fx = ixs - xs0f;
                const float fy = iys - ys0f;
                const int xs0 = (int)xs0f;
                const int ys0 = (int)ys0f;
#pragma unroll
                for (int ty = 0; ty < 2; ty++) {
#pragma unroll
                    for (int tx = 0; tx < 2; tx++) {
                        const float wt = (tx ? fx : 1.0f - fx) * (ty ? fy : 1.0f - fy);
                        const int xj = xs0 + tx;
                        const int yj = ys0 + ty;
                        if (wt != 0.0f && xj >= 0 && xj < W_IMG && yj >= 0 && yj < H_IMG) {
                            const float w = wc * wt;
                            const float4 v = __ldg(&xb[yj * W_IMG + xj]);
                            accx = fmaf(w, v.x, accx);
                            accy = fmaf(w, v.y, accy);
                            accz = fmaf(w, v.z, accz);
                        }
                    }
                }
            }
        }
    }

    float* __restrict__ o =
        out + (size_t)z * (H_IMG * W_IMG * C_IMG) + (size_t)(y * W_IMG + x) * C_IMG;
    o[0] = accx;
    o[1] = accy;
    o[2] = accz;
}

// ---------------------------------------------------------------------------
extern "C" void kernel_launch(void* const* d_in, const int* in_sizes, int n_in,
                              void* d_out, int out_size) {
    const float* xs = (const float*)d_in[0];
    float* out = (float*)d_out;

    {
        const int total = B_IMG * H_IMG * W_IMG;
        repack_kernel<<<(total + 255) / 256, 256>>>(xs);
    }
    {
        dim3 block(32, 8, 1);
        dim3 grid(W_IMG / 32, H_IMG / 8, N_ROT * N_SHIFT * B_IMG);  // (7, 28, 420)
        fused_transform_kernel<<<grid, block>>>(out);
    }
}

// round 8
// speedup vs baseline: 1.3221x; 1.3221x over previous
#include <cuda_runtime.h>
#include <cuda_bf16.h>
#include <cstdint>

#define B_IMG 4
#define H_IMG 224
#define W_IMG 224
#define C_IMG 3
#define N_SHIFT 21
#define N_ROT 5

// Padded float4 copy of the input: [B][H][W] -> float4(c0,c1,c2,0)
__device__ float4 g_xpad[B_IMG * H_IMG * W_IMG];

// Rotation cos/sin for ANGLES = [-0.5236, -0.2618, 0.0, 0.2618, 0.5236]
__constant__ float c_cos[N_ROT] = {0.86602479f, 0.96592567f, 1.0f, 0.96592567f, 0.86602479f};
__constant__ float c_sin[N_ROT] = {-0.50000106f, -0.25881964f, 0.0f, 0.25881964f, 0.50000106f};

// Integer parts of the shift offsets (floor(sdx), floor(sdy)).
// s order: up p=1..5 (sdy=+p/2), down p=1..5 (sdy=-p/2),
//          left p=1..5 (sdx=+p/2), right p=1..5 (sdx=-p/2), right p=0.
__constant__ int c_isdx[N_SHIFT] = {
    0, 0, 0, 0, 0,
    0, 0, 0, 0, 0,
    0, 1, 1, 2, 2,
    -1, -1, -2, -2, -3,
    0};
__constant__ int c_isdy[N_SHIFT] = {
    0, 1, 1, 2, 2,
    -1, -1, -2, -2, -3,
    0, 0, 0, 0, 0,
    0, 0, 0, 0, 0,
    0};

// Shift categories by fractional part:
//   A: frac(sdy)=0.5  -> NY=3, NX=2
//   B: frac(sdx)=0.5  -> NX=3, NY=2
//   C: integer shifts -> 2x2
__constant__ int c_sA[6] = {0, 2, 4, 5, 7, 9};
__constant__ int c_sB[6] = {10, 12, 14, 15, 17, 19};
__constant__ int c_sC[9] = {1, 3, 6, 8, 11, 13, 16, 18, 20};

// ---------------------------------------------------------------------------
// Kernel 1: repack NHWC float3 -> float4 plane (one LDG.128 per tap later)
// ---------------------------------------------------------------------------
__global__ void repack_kernel(const float* __restrict__ in) {
    int p = blockIdx.x * blockDim.x + threadIdx.x;
    const int total = B_IMG * H_IMG * W_IMG;
    if (p >= total) return;
    float c0 = in[p * 3 + 0];
    float c1 = in[p * 3 + 1];
    float c2 = in[p * 3 + 2];
    g_xpad[p] = make_float4(c0, c1, c2, 0.0f);
}

// ---------------------------------------------------------------------------
// Kernel 2: separable fused shift+rotate resample, branch-free taps.
// CAT selects the shift subset; NX/NY are the compile-time stencil sizes.
// blockIdx.z enumerates (r, s-in-category, b); true output z reconstructed.
// ---------------------------------------------------------------------------
template <int CAT, int NX, int NY>
__global__ __launch_bounds__(256) void fused_sep_kernel(float* __restrict__ out) {
    const int x = blockIdx.x * 32 + threadIdx.x;
    const int y = blockIdx.y * 8 + threadIdx.y;

    const unsigned zc = blockIdx.z;
    const unsigned b = zc & 3u;
    const unsigned t = zc >> 2;
    constexpr unsigned NSH = (CAT == 2) ? 9u : 6u;
    const unsigned r = t / NSH;                 // const-div -> umulhi
    const unsigned si = t - r * NSH;
    const int s = (CAT == 0) ? c_sA[si] : (CAT == 1) ? c_sB[si] : c_sC[si];
    const unsigned zout = (r * N_SHIFT + (unsigned)s) * 4u + b;

    // align_corners=True grid + rotation
    const float inv = 2.0f / (float)(W_IMG - 1);
    const float gx = fmaf((float)x, inv, -1.0f);
    const float gy = fmaf((float)y, inv, -1.0f);
    const float ca = c_cos[r];
    const float sa = c_sin[r];
    const float half = 0.5f * (float)(W_IMG - 1);   // 111.5
    const float ix = (gx * ca + gy * sa + 1.0f) * half;
    const float iy = (-gx * sa + gy * ca + 1.0f) * half;

    const float x0f = floorf(ix);
    const float y0f = floorf(iy);
    const float wx = ix - x0f;
    const float wy = iy - y0f;
    const int x0 = (int)x0f;
    const int y0 = (int)y0f;

    // Stage-2 corner weights with corner validity folded in.
    const float a0 = ((unsigned)x0 <= (unsigned)(W_IMG - 1)) ? (1.0f - wx) : 0.0f;
    const float a1 = ((unsigned)(x0 + 1) <= (unsigned)(W_IMG - 1)) ? wx : 0.0f;
    const float b0 = ((unsigned)y0 <= (unsigned)(H_IMG - 1)) ? (1.0f - wy) : 0.0f;
    const float b1 = ((unsigned)(y0 + 1) <= (unsigned)(H_IMG - 1)) ? wy : 0.0f;

    // Separable composed weights. frac(shift) is 0.5 on the 3-tap axis, 0 else.
    float Wx[NX];
    float Wy[NY];
    if constexpr (NX == 2) {
        Wx[0] = a0; Wx[1] = a1;
    } else {
        Wx[0] = 0.5f * a0; Wx[1] = 0.5f * (a0 + a1); Wx[2] = 0.5f * a1;
    }
    if constexpr (NY == 2) {
        Wy[0] = b0; Wy[1] = b1;
    } else {
        Wy[0] = 0.5f * b0; Wy[1] = 0.5f * (b0 + b1); Wy[2] = 0.5f * b1;
    }

    // Source tap base (floor(x0+sdx) = x0 + floor(sdx) since frac(sdx) in {0,.5})
    const int xs = x0 + c_isdx[s];
    const int ys = y0 + c_isdy[s];

    // Stage-1 source validity: zero weight + clamp index (safe load).
    int xcl[NX];
    int ro[NY];
#pragma unroll
    for (int i = 0; i < NX; i++) {
        const int xc = xs + i;
        if ((unsigned)xc > (unsigned)(W_IMG - 1)) Wx[i] = 0.0f;
        xcl[i] = min(max(xc, 0), W_IMG - 1);
    }
#pragma unroll
    for (int j = 0; j < NY; j++) {
        const int yc = ys + j;
        if ((unsigned)yc > (unsigned)(H_IMG - 1)) Wy[j] = 0.0f;
        ro[j] = min(max(yc, 0), H_IMG - 1) * W_IMG;
    }

    const float4* __restrict__ xb = g_xpad + b * (H_IMG * W_IMG);

    float accx = 0.f, accy = 0.f, accz = 0.f;
#pragma unroll
    for (int j = 0; j < NY; j++) {
        float rx = 0.f, ry = 0.f, rz = 0.f;
#pragma unroll
        for (int i = 0; i < NX; i++) {
            const float4 v = __ldg(&xb[ro[j] + xcl[i]]);
            rx = fmaf(Wx[i], v.x, rx);
            ry = fmaf(Wx[i], v.y, ry);
            rz = fmaf(Wx[i], v.z, rz);
        }
        accx = fmaf(Wy[j], rx, accx);
        accy = fmaf(Wy[j], ry, accy);
        accz = fmaf(Wy[j], rz, accz);
    }

    float* __restrict__ o =
        out + (size_t)zout * (H_IMG * W_IMG * C_IMG) + (size_t)(y * W_IMG + x) * C_IMG;
    o[0] = accx;
    o[1] = accy;
    o[2] = accz;
}

// ---------------------------------------------------------------------------
extern "C" void kernel_launch(void* const* d_in, const int* in_sizes, int n_in,
                              void* d_out, int out_size) {
    const float* xs = (const float*)d_in[0];
    float* out = (float*)d_out;

    {
        const int total = B_IMG * H_IMG * W_IMG;
        repack_kernel<<<(total + 255) / 256, 256>>>(xs);
    }
    dim3 block(32, 8, 1);
    // Category A: 6 shifts (half-pixel y) -> NY=3, NX=2
    fused_sep_kernel<0, 2, 3><<<dim3(W_IMG / 32, H_IMG / 8, 6 * N_ROT * B_IMG), block>>>(out);
    // Category B: 6 shifts (half-pixel x) -> NX=3, NY=2
    fused_sep_kernel<1, 3, 2><<<dim3(W_IMG / 32, H_IMG / 8, 6 * N_ROT * B_IMG), block>>>(out);
    // Category C: 9 integer shifts -> 2x2
    fused_sep_kernel<2, 2, 2><<<dim3(W_IMG / 32, H_IMG / 8, 9 * N_ROT * B_IMG), block>>>(out);
}

// round 10
// speedup vs baseline: 1.3562x; 1.0258x over previous
#include <cuda_runtime.h>
#include <cuda_bf16.h>
#include <cstdint>

#define B_IMG 4
#define H_IMG 224
#define W_IMG 224
#define C_IMG 3
#define N_SHIFT 21
#define N_ROT 5

// Padded float4 copy of the input: [B][H][W] -> float4(c0,c1,c2,0)
__device__ float4 g_xpad[B_IMG * H_IMG * W_IMG];

// Rotation cos/sin for ANGLES = [-0.5236, -0.2618, 0.0, 0.2618, 0.5236]
__constant__ float c_cos[N_ROT] = {0.86602479f, 0.96592567f, 1.0f, 0.96592567f, 0.86602479f};
__constant__ float c_sin[N_ROT] = {-0.50000106f, -0.25881964f, 0.0f, 0.25881964f, 0.50000106f};

// Integer parts of the shift offsets (floor(sdx), floor(sdy)).
__constant__ int c_isdx[N_SHIFT] = {
    0, 0, 0, 0, 0,
    0, 0, 0, 0, 0,
    0, 1, 1, 2, 2,
    -1, -1, -2, -2, -3,
    0};
__constant__ int c_isdy[N_SHIFT] = {
    0, 1, 1, 2, 2,
    -1, -1, -2, -2, -3,
    0, 0, 0, 0, 0,
    0, 0, 0, 0, 0,
    0};

// Shift categories by fractional part:
//   A: frac(sdy)=0.5  -> NY=3, NX=2
//   B: frac(sdx)=0.5  -> NX=3, NY=2
//   C: integer shifts -> 2x2
__constant__ int c_sA[6] = {0, 2, 4, 5, 7, 9};
__constant__ int c_sB[6] = {10, 12, 14, 15, 17, 19};
__constant__ int c_sC[9] = {1, 3, 6, 8, 11, 13, 16, 18, 20};

// ---------------------------------------------------------------------------
// Kernel 1: repack NHWC float3 -> float4 plane (one LDG.128 per tap later)
// ---------------------------------------------------------------------------
__global__ void repack_kernel(const float* __restrict__ in) {
    int p = blockIdx.x * blockDim.x + threadIdx.x;
    const int total = B_IMG * H_IMG * W_IMG;
    if (p >= total) return;
    float c0 = in[p * 3 + 0];
    float c1 = in[p * 3 + 1];
    float c2 = in[p * 3 + 2];
    g_xpad[p] = make_float4(c0, c1, c2, 0.0f);
}

// ---------------------------------------------------------------------------
// Kernel 2: separable fused shift+rotate resample, branch-free taps,
// smem-staged coalesced float4 output stores.
// ---------------------------------------------------------------------------
template <int CAT, int NX, int NY>
__global__ __launch_bounds__(256) void fused_sep_kernel(float* __restrict__ out) {
    // 8 rows x (32 px * 3 ch) floats = 3072 B staging tile
    __shared__ float s_out[8][96];

    const int tx = threadIdx.x;
    const int ty = threadIdx.y;
    const int x = blockIdx.x * 32 + tx;
    const int y = blockIdx.y * 8 + ty;

    const unsigned zc = blockIdx.z;
    const unsigned b = zc & 3u;
    const unsigned t = zc >> 2;
    constexpr unsigned NSH = (CAT == 2) ? 9u : 6u;
    const unsigned r = t / NSH;                 // const-div -> umulhi
    const unsigned si = t - r * NSH;
    const int s = (CAT == 0) ? c_sA[si] : (CAT == 1) ? c_sB[si] : c_sC[si];
    const unsigned zout = (r * N_SHIFT + (unsigned)s) * 4u + b;

    // align_corners=True grid + rotation
    const float inv = 2.0f / (float)(W_IMG - 1);
    const float gx = fmaf((float)x, inv, -1.0f);
    const float gy = fmaf((float)y, inv, -1.0f);
    const float ca = c_cos[r];
    const float sa = c_sin[r];
    const float half = 0.5f * (float)(W_IMG - 1);   // 111.5
    const float ix = (gx * ca + gy * sa + 1.0f) * half;
    const float iy = (-gx * sa + gy * ca + 1.0f) * half;

    const float x0f = floorf(ix);
    const float y0f = floorf(iy);
    const float wx = ix - x0f;
    const float wy = iy - y0f;
    const int x0 = (int)x0f;
    const int y0 = (int)y0f;

    // Stage-2 corner weights with corner validity folded in.
    const float a0 = ((unsigned)x0 <= (unsigned)(W_IMG - 1)) ? (1.0f - wx) : 0.0f;
    const float a1 = ((unsigned)(x0 + 1) <= (unsigned)(W_IMG - 1)) ? wx : 0.0f;
    const float b0 = ((unsigned)y0 <= (unsigned)(H_IMG - 1)) ? (1.0f - wy) : 0.0f;
    const float b1 = ((unsigned)(y0 + 1) <= (unsigned)(H_IMG - 1)) ? wy : 0.0f;

    // Separable composed weights. frac(shift) is 0.5 on the 3-tap axis, 0 else.
    float Wx[NX];
    float Wy[NY];
    if constexpr (NX == 2) {
        Wx[0] = a0; Wx[1] = a1;
    } else {
        Wx[0] = 0.5f * a0; Wx[1] = 0.5f * (a0 + a1); Wx[2] = 0.5f * a1;
    }
    if constexpr (NY == 2) {
        Wy[0] = b0; Wy[1] = b1;
    } else {
        Wy[0] = 0.5f * b0; Wy[1] = 0.5f * (b0 + b1); Wy[2] = 0.5f * b1;
    }

    // Source tap base (floor(x0+sdx) = x0 + floor(sdx) since frac(sdx) in {0,.5})
    const int xs = x0 + c_isdx[s];
    const int ys = y0 + c_isdy[s];

    // Stage-1 source validity: zero weight + clamp index (safe load).
    int xcl[NX];
    int ro[NY];
#pragma unroll
    for (int i = 0; i < NX; i++) {
        const int xc = xs + i;
        if ((unsigned)xc > (unsigned)(W_IMG - 1)) Wx[i] = 0.0f;
        xcl[i] = min(max(xc, 0), W_IMG - 1);
    }
#pragma unroll
    for (int j = 0; j < NY; j++) {
        const int yc = ys + j;
        if ((unsigned)yc > (unsigned)(H_IMG - 1)) Wy[j] = 0.0f;
        ro[j] = min(max(yc, 0), H_IMG - 1) * W_IMG;
    }

    const float4* __restrict__ xb = g_xpad + b * (H_IMG * W_IMG);

    float accx = 0.f, accy = 0.f, accz = 0.f;
#pragma unroll
    for (int j = 0; j < NY; j++) {
        float rx = 0.f, ry = 0.f, rz = 0.f;
#pragma unroll
        for (int i = 0; i < NX; i++) {
            const float4 v = __ldg(&xb[ro[j] + xcl[i]]);
            rx = fmaf(Wx[i], v.x, rx);
            ry = fmaf(Wx[i], v.y, ry);
            rz = fmaf(Wx[i], v.z, rz);
        }
        accx = fmaf(Wy[j], rx, accx);
        accy = fmaf(Wy[j], ry, accy);
        accz = fmaf(Wy[j], rz, accz);
    }

    // Stage into smem (stride-3 writes: 3 coprime 32 -> conflict-free)
    s_out[ty][tx * 3 + 0] = accx;
    s_out[ty][tx * 3 + 1] = accy;
    s_out[ty][tx * 3 + 2] = accz;
    __syncthreads();

    // Coalesced float4 drain: 8 rows x 24 float4 = 192 stores.
    const int tid = ty * 32 + tx;
    if (tid < 192) {
        const int row = tid / 24;        // const-div
        const int q = tid - row * 24;
        const float4 v = reinterpret_cast<const float4*>(&s_out[row][0])[q];
        // global float offset of this row's tile start (all 16B-aligned)
        const size_t go = (size_t)zout * (H_IMG * W_IMG * C_IMG)
                        + (size_t)((blockIdx.y * 8 + row) * W_IMG + blockIdx.x * 32) * C_IMG;
        reinterpret_cast<float4*>(out + go)[q] = v;
    }
}

// ---------------------------------------------------------------------------
extern "C" void kernel_launch(void* const* d_in, const int* in_sizes, int n_in,
                              void* d_out, int out_size) {
    const float* xs = (const float*)d_in[0];
    float* out = (float*)d_out;

    {
        const int total = B_IMG * H_IMG * W_IMG;
        repack_kernel<<<(total + 255) / 256, 256>>>(xs);
    }
    dim3 block(32, 8, 1);
    // Category A: 6 shifts (half-pixel y) -> NY=3, NX=2
    fused_sep_kernel<0, 2, 3><<<dim3(W_IMG / 32, H_IMG / 8, 6 * N_ROT * B_IMG), block>>>(out);
    // Category B: 6 shifts (half-pixel x) -> NX=3, NY=2
    fused_sep_kernel<1, 3, 2><<<dim3(W_IMG / 32, H_IMG / 8, 6 * N_ROT * B_IMG), block>>>(out);
    // Category C: 9 integer shifts -> 2x2
    fused_sep_kernel<2, 2, 2><<<dim3(W_IMG / 32, H_IMG / 8, 9 * N_ROT * B_IMG), block>>>(out);
}

// round 17
// speedup vs baseline: 1.9818x; 1.4613x over previous
#include <cuda_runtime.h>
#include <cuda_bf16.h>
#include <cstdint>

#define B_IMG 4
#define H_IMG 224
#define W_IMG 224
#define C_IMG 3
#define HWC (H_IMG * W_IMG * C_IMG)
#define N_SHIFT 21
#define N_ROT 5

// Padded float4 copy of the input: [B][H][W] -> float4(c0,c1,c2,0)
__device__ float4 g_xpad[B_IMG * H_IMG * W_IMG];

// Rotation cos/sin for ANGLES = [-0.5236, -0.2618, 0.0, 0.2618, 0.5236]
__constant__ float c_cos[N_ROT] = {0.86602479f, 0.96592567f, 1.0f, 0.96592567f, 0.86602479f};
__constant__ float c_sin[N_ROT] = {-0.50000106f, -0.25881964f, 0.0f, 0.25881964f, 0.50000106f};

// Shift IDs per family (runtime-indexed in the drain -> __constant__).
// A:  half-pixel y shifts (3-tap y).  Cv: integer-y + center (2-tap y).
// B:  half-pixel x shifts (3-tap x).  Ch: integer-x (2-tap x).
__constant__ int c_sA[6]  = {0, 2, 4, 5, 7, 9};
__constant__ int c_sCv[5] = {20, 1, 3, 6, 8};
__constant__ int c_sB[6]  = {10, 12, 14, 15, 17, 19};
__constant__ int c_sCh[4] = {11, 13, 16, 18};

// d-offset tables as constexpr switches: only used with compile-time k
// (fully unrolled loops), so they fold to immediates.
template <bool YAXIS, int INST>
__device__ __forceinline__ constexpr int tab_d(int k) {
    if constexpr (YAXIS) {
        if constexpr (INST == 0) {          // A: {0,1,2,-1,-2,-3}
            switch (k) { case 0: return 0; case 1: return 1; case 2: return 2;
                         case 3: return -1; case 4: return -2; default: return -3; }
        } else {                            // Cv: {0,1,2,-1,-2}
            switch (k) { case 0: return 0; case 1: return 1; case 2: return 2;
                         case 3: return -1; default: return -2; }
        }
    } else {
        if constexpr (INST == 0) {          // B: {0,1,2,-1,-2,-3}
            switch (k) { case 0: return 0; case 1: return 1; case 2: return 2;
                         case 3: return -1; case 4: return -2; default: return -3; }
        } else {                            // Ch: {1,2,-1,-2}
            switch (k) { case 0: return 1; case 1: return 2;
                         case 2: return -1; default: return -2; }
        }
    }
}

// ---------------------------------------------------------------------------
// Kernel 1: repack NHWC float3 -> float4 plane (one LDG.128 per tap later)
// ---------------------------------------------------------------------------
__global__ void repack_kernel(const float* __restrict__ in) {
    int p = blockIdx.x * blockDim.x + threadIdx.x;
    const int total = B_IMG * H_IMG * W_IMG;
    if (p >= total) return;
    float c0 = in[p * 3 + 0];
    float c1 = in[p * 3 + 1];
    float c2 = in[p * 3 + 2];
    g_xpad[p] = make_float4(c0, c1, c2, 0.0f);
}

// Common per-thread rotation setup
struct RotCtx {
    int x0, y0;
    float a0, a1, b0, b1;   // stage-2 corner weights with validity folded
};

__device__ __forceinline__ RotCtx rot_setup(int x, int y, unsigned r) {
    const float inv = 2.0f / (float)(W_IMG - 1);
    const float gx = fmaf((float)x, inv, -1.0f);
    const float gy = fmaf((float)y, inv, -1.0f);
    const float ca = c_cos[r];
    const float sa = c_sin[r];
    const float half = 0.5f * (float)(W_IMG - 1);
    const float ix = (gx * ca + gy * sa + 1.0f) * half;
    const float iy = (-gx * sa + gy * ca + 1.0f) * half;
    const float x0f = floorf(ix);
    const float y0f = floorf(iy);
    const float wx = ix - x0f;
    const float wy = iy - y0f;
    RotCtx c;
    c.x0 = (int)x0f;
    c.y0 = (int)y0f;
    c.a0 = ((unsigned)c.x0 <= (unsigned)(W_IMG - 1)) ? (1.0f - wx) : 0.0f;
    c.a1 = ((unsigned)(c.x0 + 1) <= (unsigned)(W_IMG - 1)) ? wx : 0.0f;
    c.b0 = ((unsigned)c.y0 <= (unsigned)(H_IMG - 1)) ? (1.0f - wy) : 0.0f;
    c.b1 = ((unsigned)(c.y0 + 1) <= (unsigned)(H_IMG - 1)) ? wy : 0.0f;
    return c;
}

// Shared drain: smem tiles -> coalesced float4 global stores
template <int NOUT, int INST, bool XAXIS>
__device__ __forceinline__ void drain(float (*s_out)[8][96], float* __restrict__ out,
                                      unsigned r, unsigned b, int tid) {
    __syncthreads();
#pragma unroll 1
    for (int i = tid; i < NOUT * 192; i += 256) {
        const int k = i / 192;
        const int rem = i - k * 192;
        const int row = rem / 24;
        const int q = rem - row * 24;
        int s;
        if constexpr (XAXIS) s = (INST == 0) ? c_sB[k] : c_sCh[k];
        else                 s = (INST == 0) ? c_sA[k] : c_sCv[k];
        const unsigned zout = (r * N_SHIFT + (unsigned)s) * 4u + b;
        const size_t go = (size_t)zout * HWC
                        + (size_t)(((blockIdx.y * 8 + row) * W_IMG + blockIdx.x * 32) * 3);
        const float4 v = reinterpret_cast<const float4*>(&s_out[k][row][0])[q];
        reinterpret_cast<float4*>(out + go)[q] = v;
    }
}

// ---------------------------------------------------------------------------
// Y-family kernel: all outputs share cols (x0, x0+1); rows ROW_LO..ROW_LO+NR-1.
// ---------------------------------------------------------------------------
template <int INST, int NOUT, int ROW_LO, int NR, bool HALF>
__global__ __launch_bounds__(256) void axisY_kernel(float* __restrict__ out) {
    __shared__ float s_out[NOUT][8][96];
    const int tx = threadIdx.x, ty = threadIdx.y;
    const int x = blockIdx.x * 32 + tx;
    const int y = blockIdx.y * 8 + ty;
    const unsigned z = blockIdx.z;
    const unsigned b = z & 3u;
    const unsigned r = z >> 2;

    const RotCtx c = rot_setup(x, y, r);
    const int xc0 = min(max(c.x0, 0), W_IMG - 1);
    const int xc1 = min(max(c.x0 + 1, 0), W_IMG - 1);
    const float4* __restrict__ xb = g_xpad + b * (H_IMG * W_IMG);

    float rvx[NR], rvy[NR], rvz[NR];
#pragma unroll
    for (int d = 0; d < NR; d++) {
        const int row = c.y0 + ROW_LO + d;
        const float vf = ((unsigned)row <= (unsigned)(H_IMG - 1)) ? 1.0f : 0.0f;
        const int ro = min(max(row, 0), H_IMG - 1) * W_IMG;
        const float4 v0 = __ldg(&xb[ro + xc0]);
        const float4 v1 = __ldg(&xb[ro + xc1]);
        rvx[d] = (c.a0 * v0.x + c.a1 * v1.x) * vf;
        rvy[d] = (c.a0 * v0.y + c.a1 * v1.y) * vf;
        rvz[d] = (c.a0 * v0.z + c.a1 * v1.z) * vf;
    }

#pragma unroll
    for (int k = 0; k < NOUT; k++) {
        constexpr int dummy = 0; (void)dummy;
        const int d0 = tab_d<true, INST>(k) - ROW_LO;
        float ax, ay, az;
        if constexpr (HALF) {
            const float w0 = 0.5f * c.b0;
            const float w1 = 0.5f * (c.b0 + c.b1);
            const float w2 = 0.5f * c.b1;
            ax = w0 * rvx[d0] + w1 * rvx[d0 + 1] + w2 * rvx[d0 + 2];
            ay = w0 * rvy[d0] + w1 * rvy[d0 + 1] + w2 * rvy[d0 + 2];
            az = w0 * rvz[d0] + w1 * rvz[d0 + 1] + w2 * rvz[d0 + 2];
        } else {
            ax = c.b0 * rvx[d0] + c.b1 * rvx[d0 + 1];
            ay = c.b0 * rvy[d0] + c.b1 * rvy[d0 + 1];
            az = c.b0 * rvz[d0] + c.b1 * rvz[d0 + 1];
        }
        s_out[k][ty][tx * 3 + 0] = ax;
        s_out[k][ty][tx * 3 + 1] = ay;
        s_out[k][ty][tx * 3 + 2] = az;
    }
    drain<NOUT, INST, false>(s_out, out, r, b, ty * 32 + tx);
}

// ---------------------------------------------------------------------------
// X-family kernel: all outputs share rows (y0, y0+1); cols COL_LO..COL_LO+NC-1.
// ---------------------------------------------------------------------------
template <int INST, int NOUT, int COL_LO, int NC, bool HALF>
__global__ __launch_bounds__(256) void axisX_kernel(float* __restrict__ out) {
    __shared__ float s_out[NOUT][8][96];
    const int tx = threadIdx.x, ty = threadIdx.y;
    const int x = blockIdx.x * 32 + tx;
    const int y = blockIdx.y * 8 + ty;
    const unsigned z = blockIdx.z;
    const unsigned b = z & 3u;
    const unsigned r = z >> 2;

    const RotCtx c = rot_setup(x, y, r);
    const int ro0 = min(max(c.y0, 0), H_IMG - 1) * W_IMG;
    const int ro1 = min(max(c.y0 + 1, 0), H_IMG - 1) * W_IMG;
    const float4* __restrict__ xb = g_xpad + b * (H_IMG * W_IMG);

    float cvx[NC], cvy[NC], cvz[NC];
#pragma unroll
    for (int d = 0; d < NC; d++) {
        const int col = c.x0 + COL_LO + d;
        const float vf = ((unsigned)col <= (unsigned)(W_IMG - 1)) ? 1.0f : 0.0f;
        const int xc = min(max(col, 0), W_IMG - 1);
        const float4 v0 = __ldg(&xb[ro0 + xc]);
        const float4 v1 = __ldg(&xb[ro1 + xc]);
        cvx[d] = (c.b0 * v0.x + c.b1 * v1.x) * vf;
        cvy[d] = (c.b0 * v0.y + c.b1 * v1.y) * vf;
        cvz[d] = (c.b0 * v0.z + c.b1 * v1.z) * vf;
    }

#pragma unroll
    for (int k = 0; k < NOUT; k++) {
        const int d0 = tab_d<false, INST>(k) - COL_LO;
        float ax, ay, az;
        if constexpr (HALF) {
            const float w0 = 0.5f * c.a0;
            const float w1 = 0.5f * (c.a0 + c.a1);
            const float w2 = 0.5f * c.a1;
            ax = w0 * cvx[d0] + w1 * cvx[d0 + 1] + w2 * cvx[d0 + 2];
            ay = w0 * cvy[d0] + w1 * cvy[d0 + 1] + w2 * cvy[d0 + 2];
            az = w0 * cvz[d0] + w1 * cvz[d0 + 1] + w2 * cvz[d0 + 2];
        } else {
            ax = c.a0 * cvx[d0] + c.a1 * cvx[d0 + 1];
            ay = c.a0 * cvy[d0] + c.a1 * cvy[d0 + 1];
            az = c.a0 * cvz[d0] + c.a1 * cvz[d0 + 1];
        }
        s_out[k][ty][tx * 3 + 0] = ax;
        s_out[k][ty][tx * 3 + 1] = ay;
        s_out[k][ty][tx * 3 + 2] = az;
    }
    drain<NOUT, INST, true>(s_out, out, r, b, ty * 32 + tx);
}

// ---------------------------------------------------------------------------
extern "C" void kernel_launch(void* const* d_in, const int* in_sizes, int n_in,
                              void* d_out, int out_size) {
    const float* xs = (const float*)d_in[0];
    float* out = (float*)d_out;

    {
        const int total = B_IMG * H_IMG * W_IMG;
        repack_kernel<<<(total + 255) / 256, 256>>>(xs);
    }
    dim3 blk(32, 8, 1);
    dim3 grd(W_IMG / 32, H_IMG / 8, N_ROT * B_IMG);  // (7, 28, 20)

    // A:  6 half-y shifts, rows y0-3..y0+4  (3-tap y)
    axisY_kernel<0, 6, -3, 8, true><<<grd, blk>>>(out);
    // Cv: 5 integer-y shifts (incl center), rows y0-2..y0+3 (2-tap y)
    axisY_kernel<1, 5, -2, 6, false><<<grd, blk>>>(out);
    // B:  6 half-x shifts, cols x0-3..x0+4 (3-tap x)
    axisX_kernel<0, 6, -3, 8, true><<<grd, blk>>>(out);
    // Ch: 4 integer-x shifts, cols x0-2..x0+3 (2-tap x)
    axisX_kernel<1, 4, -2, 6, false><<<grd, blk>>>(out);
}